// round 12
// baseline (speedup 1.0000x reference)
#include <cuda_runtime.h>
#include <cuda_bf16.h>
#include <math.h>

// ---------------- problem constants ----------------
#define BATCHN 2048
#define SEQT   80
#define EMBD   100
#define KPADE  128                 // EMBD padded to 128 (2 x 64 chunks)
#define HU     512
#define ROWSTR (SEQT * HU)
#define VOCABN 10000
#define MTOT   (BATCHN * SEQT)
#define NTILES (MTOT / 128)        // 1280

#define SSTR 72                    // padded smem row stride in halves

// ---------------- device scratch ----------------
__device__ __nv_bfloat16  g_x [(size_t)BATCHN * SEQT * HU];   // input projections bf16
__device__ __nv_bfloat16  g_sb[(size_t)BATCHN * SEQT * HU];   // hidden states bf16
__device__ __nv_bfloat16  g_Ub[4 * HU * HU];                  // U bf16 [K][N]
__device__ __nv_bfloat16  g_Wb[3 * HU * HU];                  // W2..W4 bf16 [K][N]
__device__ __nv_bfloat16  g_W1b[KPADE * HU];                  // W1 bf16, K padded
__device__ __nv_bfloat16  g_embb[(size_t)VOCABN * KPADE];     // emb bf16, K padded
__device__ int            g_flags[4 * 16 * 8];                // per layer/rowgroup/colblock

// ---------------- PTX helpers ----------------
__device__ __forceinline__ unsigned smem_u32(const void* p) {
    return (unsigned)__cvta_generic_to_shared(p);
}
__device__ __forceinline__ void ldsm_x4(unsigned& r0, unsigned& r1, unsigned& r2, unsigned& r3, unsigned a) {
    asm volatile("ldmatrix.sync.aligned.m8n8.x4.shared.b16 {%0,%1,%2,%3},[%4];"
                 : "=r"(r0), "=r"(r1), "=r"(r2), "=r"(r3) : "r"(a));
}
__device__ __forceinline__ void ldsm_x4t(unsigned& r0, unsigned& r1, unsigned& r2, unsigned& r3, unsigned a) {
    asm volatile("ldmatrix.sync.aligned.m8n8.x4.trans.shared.b16 {%0,%1,%2,%3},[%4];"
                 : "=r"(r0), "=r"(r1), "=r"(r2), "=r"(r3) : "r"(a));
}
__device__ __forceinline__ void mma16816(float* c,
                                         unsigned a0, unsigned a1, unsigned a2, unsigned a3,
                                         unsigned b0, unsigned b1) {
    asm volatile("mma.sync.aligned.m16n8k16.row.col.f32.bf16.bf16.f32 "
                 "{%0,%1,%2,%3},{%4,%5,%6,%7},{%8,%9},{%0,%1,%2,%3};"
                 : "+f"(c[0]), "+f"(c[1]), "+f"(c[2]), "+f"(c[3])
                 : "r"(a0), "r"(a1), "r"(a2), "r"(a3), "r"(b0), "r"(b1));
}
__device__ __forceinline__ void cp16(void* dst, const void* src) {
    unsigned d = smem_u32(dst);
    asm volatile("cp.async.cg.shared.global [%0],[%1],16;" :: "r"(d), "l"(src));
}
__device__ __forceinline__ void cp_commit() { asm volatile("cp.async.commit_group;"); }
__device__ __forceinline__ void cp_wait0()  { asm volatile("cp.async.wait_group 0;"); }
__device__ __forceinline__ void cp_wait1()  { asm volatile("cp.async.wait_group 1;"); }
__device__ __forceinline__ void cp_wait2()  { asm volatile("cp.async.wait_group 2;"); }
__device__ __forceinline__ int ld_acq(const int* p) {
    int v;
    asm volatile("ld.acquire.gpu.global.s32 %0,[%1];" : "=r"(v) : "l"(p) : "memory");
    return v;
}
__device__ __forceinline__ void st_rel(int* p, int v) {
    asm volatile("st.release.gpu.global.s32 [%0],%1;" :: "l"(p), "r"(v) : "memory");
}
__device__ __forceinline__ float tanh_fast(float x) {
    float y;
    asm("tanh.approx.f32 %0,%1;" : "=f"(y) : "f"(x));
    return y;
}

// ---------------- mma building block ----------------
// one k16 slice: A frags (128x64 chunk, stride SSTR), B frags from resident
// U chunk (64x64, stride SSTR). acc[2][4][4]. warp tile 32(m) x 32(n).
__device__ __forceinline__ void mma_k16(float acc[2][4][4],
                                        const __nv_bfloat16* Ab,
                                        const __nv_bfloat16* Uk,
                                        int kt, int lane, int wm, int wn)
{
    unsigned af0[4];
    unsigned af1[4];
    unsigned bf0[4];
    unsigned bf1[4];
    {
        unsigned ad = smem_u32(Ab + (wm + (lane & 15)) * SSTR + kt * 16 + ((lane >> 4) << 3));
        ldsm_x4(af0[0], af0[1], af0[2], af0[3], ad);
    }
    {
        unsigned ad = smem_u32(Ab + (wm + 16 + (lane & 15)) * SSTR + kt * 16 + ((lane >> 4) << 3));
        ldsm_x4(af1[0], af1[1], af1[2], af1[3], ad);
    }
    {
        unsigned ad = smem_u32(Uk + (kt * 16 + (lane & 15)) * SSTR + wn + ((lane >> 4) << 3));
        ldsm_x4t(bf0[0], bf0[1], bf0[2], bf0[3], ad);
    }
    {
        unsigned ad = smem_u32(Uk + (kt * 16 + (lane & 15)) * SSTR + wn + 16 + ((lane >> 4) << 3));
        ldsm_x4t(bf1[0], bf1[1], bf1[2], bf1[3], ad);
    }
    mma16816(acc[0][0], af0[0], af0[1], af0[2], af0[3], bf0[0], bf0[1]);
    mma16816(acc[0][1], af0[0], af0[1], af0[2], af0[3], bf0[2], bf0[3]);
    mma16816(acc[0][2], af0[0], af0[1], af0[2], af0[3], bf1[0], bf1[1]);
    mma16816(acc[0][3], af0[0], af0[1], af0[2], af0[3], bf1[2], bf1[3]);
    mma16816(acc[1][0], af1[0], af1[1], af1[2], af1[3], bf0[0], bf0[1]);
    mma16816(acc[1][1], af1[0], af1[1], af1[2], af1[3], bf0[2], bf0[3]);
    mma16816(acc[1][2], af1[0], af1[1], af1[2], af1[3], bf1[0], bf1[1]);
    mma16816(acc[1][3], af1[0], af1[1], af1[2], af1[3], bf1[2], bf1[3]);
}

// async-load a 128x64 bf16 chunk; src at (row0, k0), row stride lda
__device__ __forceinline__ void load_chunk(__nv_bfloat16* dst,
                                           const __nv_bfloat16* src, long lda, int tid)
{
    #pragma unroll
    for (int j = 0; j < 4; j++) {
        int idx = tid + j * 256;
        int r   = idx >> 3;
        int c8  = (idx & 7) << 3;
        cp16(dst + r * SSTR + c8, src + (long)r * lda + c8);
    }
}
__device__ __forceinline__ void load_chunk_g(__nv_bfloat16* dst,
                                             const __nv_bfloat16* embb,
                                             const int* toks, int rowBase, int kofs, int tid)
{
    #pragma unroll
    for (int j = 0; j < 4; j++) {
        int idx = tid + j * 256;
        int r   = idx >> 3;
        int c8  = (idx & 7) << 3;
        long tr = toks[rowBase + r];
        cp16(dst + r * SSTR + c8, embb + tr * KPADE + kofs + c8);
    }
}

#define SMEM_PROJ ((512 * SSTR + 2 * 128 * SSTR) * 2)   // 110592
#define SMEM_LAYER ((512 * SSTR + 3 * 128 * SSTR) * 2)  // 129024

// --------------------------------------------------------------------------
// Projection: out_bf16[M,512] = A[M,ktot] @ W[ktot,512] + bias.
// Persistent: W col-slice resident; each block loops row tiles.
// --------------------------------------------------------------------------
__global__ __launch_bounds__(256) void k_projx(
    const __nv_bfloat16* __restrict__ amat, const int* __restrict__ toks,
    const __nv_bfloat16* __restrict__ wmat, const float* __restrict__ bias,
    __nv_bfloat16* __restrict__ outc, int ktot, int gather)
{
    extern __shared__ __align__(16) char smraw[];
    __nv_bfloat16* Us  = (__nv_bfloat16*)smraw;
    __nv_bfloat16* Ab0 = Us + 512 * SSTR;
    __nv_bfloat16* Ab1 = Ab0 + 128 * SSTR;

    const int tid  = threadIdx.x;
    const int lane = tid & 31;
    const int wid  = tid >> 5;
    const int wm   = (wid >> 1) * 32;
    const int wn   = (wid & 1) * 32;
    const int colBase = blockIdx.x * 64;

    for (int i = tid; i < ktot * 8; i += 256) {
        int r  = i >> 3;
        int c8 = (i & 7) << 3;
        *(uint4*)&Us[r * SSTR + c8] = *(const uint4*)&wmat[(long)r * HU + colBase + c8];
    }
    __syncthreads();

    const int nch = ktot >> 6;
    const int cr = lane >> 2;
    const int cc = (lane & 3) * 2;

    for (int tile = blockIdx.y; tile < NTILES; tile += gridDim.y) {
        const int rowBase = tile * 128;
        if (gather) { load_chunk_g(Ab0, amat, toks, rowBase, 0, tid); }
        else        { load_chunk(Ab0, amat + (long)rowBase * ktot, (long)ktot, tid); }
        cp_commit();

        float acc[2][4][4];
        #pragma unroll
        for (int i = 0; i < 2; i++) {
            #pragma unroll
            for (int j = 0; j < 4; j++) {
                #pragma unroll
                for (int e = 0; e < 4; e++) { acc[i][j][e] = 0.f; }
            }
        }

        for (int kc = 0; kc < nch; kc++) {
            __nv_bfloat16* cur = (kc & 1) ? Ab1 : Ab0;
            __nv_bfloat16* nxt = (kc & 1) ? Ab0 : Ab1;
            if (kc + 1 < nch) {
                if (gather) { load_chunk_g(nxt, amat, toks, rowBase, (kc + 1) * 64, tid); }
                else        { load_chunk(nxt, amat + (long)rowBase * ktot + (kc + 1) * 64, (long)ktot, tid); }
                cp_commit();
                cp_wait1();
            } else {
                cp_wait0();
            }
            __syncthreads();
            const __nv_bfloat16* Uk = Us + kc * 64 * SSTR;
            for (int kt = 0; kt < 4; kt++) { mma_k16(acc, cur, Uk, kt, lane, wm, wn); }
            __syncthreads();
        }

        #pragma unroll
        for (int mm = 0; mm < 2; mm++) {
            #pragma unroll
            for (int nn = 0; nn < 4; nn++) {
                const int col = colBase + wn + nn * 8 + cc;
                #pragma unroll
                for (int hf = 0; hf < 2; hf++) {
                    const int row = rowBase + wm + mm * 16 + cr + hf * 8;
                    float v0 = acc[mm][nn][hf * 2 + 0] + bias[col];
                    float v1 = acc[mm][nn][hf * 2 + 1] + bias[col + 1];
                    *(__nv_bfloat162*)&outc[(long)row * HU + col] = __floats2bfloat162_rn(v0, v1);
                }
            }
        }
    }
}

// --------------------------------------------------------------------------
// Persistent per-layer recurrence. Grid (8,16) = 128 resident blocks.
// Per-producer flags: flag[rb*8+cb] = steps completed. A block starts each
// step with its OWN chunk (kept in smem from its epilogue), wraps over the
// other 7 with a 3-buffer cp.async ring; waits overlap with compute.
// --------------------------------------------------------------------------
__global__ __launch_bounds__(256) void k_layer(
    const __nv_bfloat16* __restrict__ u,
    const __nv_bfloat16* __restrict__ xin,
    __nv_bfloat16* __restrict__ hseq,
    int* __restrict__ flg)
{
    extern __shared__ __align__(16) char smraw[];
    __nv_bfloat16* Us = (__nv_bfloat16*)smraw;
    __nv_bfloat16* Ab0 = Us + 512 * SSTR;
    __nv_bfloat16* Ab1 = Ab0 + 128 * SSTR;
    __nv_bfloat16* Ab2 = Ab1 + 128 * SSTR;
    __nv_bfloat16* ring[3];
    ring[0] = Ab0; ring[1] = Ab1; ring[2] = Ab2;

    const int tid  = threadIdx.x;
    const int lane = tid & 31;
    const int wid  = tid >> 5;
    const int wm   = (wid >> 1) * 32;
    const int wn   = (wid & 1) * 32;
    const int cb   = blockIdx.x;
    const int rb   = blockIdx.y;
    const int rowBase = rb * 128;
    const int colBase = cb * 64;
    int* fbase  = flg + rb * 8;
    int* myflag = fbase + cb;

    for (int i = tid; i < 512 * 8; i += 256) {
        int r  = i >> 3;
        int c8 = (i & 7) << 3;
        *(uint4*)&Us[r * SSTR + c8] = *(const uint4*)&u[(long)r * HU + colBase + c8];
    }

    // t=0: h0 = tanh(x0) -> gmem + own-chunk smem (Ab0)
    for (int i = tid; i < 128 * 64; i += 256) {
        int r = i >> 6;
        int c = i & 63;
        long off = (long)(rowBase + r) * ROWSTR + colBase + c;
        float v = tanh_fast(__bfloat162float(xin[off]));
        __nv_bfloat16 hv = __float2bfloat16(v);
        hseq[off] = hv;
        Ab0[r * SSTR + c] = hv;
    }
    __syncthreads();
    if (tid == 0) { st_rel(myflag, 1); }

    const int cr = lane >> 2;
    const int cc = (lane & 3) * 2;

    for (int t = 1; t < SEQT; t++) {
        const __nv_bfloat16* hprev = hseq + (long)rowBase * ROWSTR + (long)(t - 1) * HU;

        // prologue: stage 1 (own stage 0 already in Ab0 from epilogue/h0)
        const int kc1 = (cb + 1) & 7;
        if (tid == 0) { while (ld_acq(fbase + kc1) < t) { } }
        __syncthreads();                                   // flags + own-chunk smem visible
        load_chunk(ring[1], hprev + kc1 * 64, (long)ROWSTR, tid);
        cp_commit();

        // hoist x_t loads (bf16x2), overlap with GEMM
        unsigned xr[16];
        {
            int q = 0;
            #pragma unroll
            for (int mm = 0; mm < 2; mm++) {
                #pragma unroll
                for (int nn = 0; nn < 4; nn++) {
                    const int col = colBase + wn + nn * 8 + cc;
                    #pragma unroll
                    for (int hf = 0; hf < 2; hf++) {
                        const int row = rowBase + wm + mm * 16 + cr + hf * 8;
                        xr[q] = *(const unsigned*)&xin[(long)row * ROWSTR + (long)t * HU + col];
                        q++;
                    }
                }
            }
        }

        float acc[2][4][4];
        #pragma unroll
        for (int i = 0; i < 2; i++) {
            #pragma unroll
            for (int j = 0; j < 4; j++) {
                #pragma unroll
                for (int e = 0; e < 4; e++) { acc[i][j][e] = 0.f; }
            }
        }

        #pragma unroll
        for (int i = 0; i < 8; i++) {
            const int kci = (cb + i) & 7;
            if (i + 2 < 8) {
                const int kcn = (cb + i + 2) & 7;
                if (tid == 0) { while (ld_acq(fbase + kcn) < t) { } }
                __syncthreads();                           // buffer (i+2)%3 free + flag ack
                load_chunk(ring[(i + 2) % 3], hprev + kcn * 64, (long)ROWSTR, tid);
                cp_commit();
                if (i > 0) { cp_wait2(); }
            } else if (i + 1 < 8) {
                cp_wait1();
            } else {
                cp_wait0();
            }
            __syncthreads();                               // stage i data visible
            const __nv_bfloat16* Uk = Us + kci * 64 * SSTR;
            for (int kt = 0; kt < 4; kt++) { mma_k16(acc, ring[i % 3], Uk, kt, lane, wm, wn); }
        }

        // epilogue: h_t = tanh(acc + x_t) -> gmem + own-chunk smem (Ab0)
        {
            int q = 0;
            #pragma unroll
            for (int mm = 0; mm < 2; mm++) {
                #pragma unroll
                for (int nn = 0; nn < 4; nn++) {
                    const int col = colBase + wn + nn * 8 + cc;
                    #pragma unroll
                    for (int hf = 0; hf < 2; hf++) {
                        const int row = rowBase + wm + mm * 16 + cr + hf * 8;
                        const int lr  = wm + mm * 16 + cr + hf * 8;
                        const int lc  = wn + nn * 8 + cc;
                        float2 xv = __bfloat1622float2(*(const __nv_bfloat162*)&xr[q]);
                        q++;
                        float v0 = tanh_fast(acc[mm][nn][hf * 2 + 0] + xv.x);
                        float v1 = tanh_fast(acc[mm][nn][hf * 2 + 1] + xv.y);
                        __nv_bfloat162 hv = __floats2bfloat162_rn(v0, v1);
                        *(__nv_bfloat162*)&hseq[(long)row * ROWSTR + (long)t * HU + col] = hv;
                        *(__nv_bfloat162*)&Ab0[lr * SSTR + lc] = hv;
                    }
                }
            }
        }
        __syncthreads();
        if (tid == 0) { st_rel(myflag, t + 1); }
    }
}

// ---------------- conversion / misc kernels ----------------
struct SrcPtrs { const float* p[7]; };

__global__ void k_convertW(SrcPtrs sp, __nv_bfloat16* __restrict__ dstU,
                           __nv_bfloat16* __restrict__ dstW)
{
    int id = blockIdx.x * 256 + threadIdx.x;        // 7 * 262144 total
    int region = id >> 18;
    int off    = id & 262143;
    float v = sp.p[region][off];
    if (region < 4) { dstU[region * 262144 + off] = __float2bfloat16(v); }
    else            { dstW[(region - 4) * 262144 + off] = __float2bfloat16(v); }
}
__global__ void k_padW1(const float* __restrict__ w1, __nv_bfloat16* __restrict__ dst) {
    int i = blockIdx.x * blockDim.x + threadIdx.x;
    if (i < KPADE * HU) {
        int k = i / HU;
        int n = i - k * HU;
        float v = (k < EMBD) ? w1[k * HU + n] : 0.f;
        dst[i] = __float2bfloat16(v);
    }
}
__global__ void k_padEmb(const float* __restrict__ emb, __nv_bfloat16* __restrict__ dst) {
    long i = (long)blockIdx.x * blockDim.x + threadIdx.x;
    if (i < (long)VOCABN * KPADE) {
        int r = (int)(i / KPADE);
        int c = (int)(i - (long)r * KPADE);
        float v = (c < EMBD) ? emb[(long)r * EMBD + c] : 0.f;
        dst[i] = __float2bfloat16(v);
    }
}
__global__ void k_reset(int* __restrict__ flg) {
    int i = blockIdx.x * blockDim.x + threadIdx.x;
    if (i < 4 * 16 * 8) { flg[i] = 0; }
}
__global__ __launch_bounds__(256) void k_head(
    const __nv_bfloat16* __restrict__ sb, const float* __restrict__ wo,
    const float* __restrict__ bo, float* __restrict__ outp)
{
    const int m = blockIdx.x * 8 + (threadIdx.x >> 5);
    const int lane = threadIdx.x & 31;
    const __nv_bfloat16* hrow = sb + (long)m * ROWSTR + (SEQT - 1) * HU;
    float s = 0.f;
    for (int k = lane; k < HU; k += 32) {
        s = fmaf(__bfloat162float(hrow[k]), wo[k], s);
    }
    #pragma unroll
    for (int o = 16; o > 0; o >>= 1) {
        s += __shfl_xor_sync(0xFFFFFFFFu, s, o);
    }
    if (lane == 0) { outp[m] = 1.f / (1.f + expf(-(s + bo[0]))); }
}

// ---------------- launch ----------------
extern "C" void kernel_launch(void* const* d_in, const int* in_sizes, int n_in,
                              void* d_out, int out_size)
{
    (void)in_sizes; (void)n_in; (void)out_size;

    const int*   tokens = (const int*)  d_in[0];
    const float* emb    = (const float*)d_in[1];
    const float* wmat[4];
    const float* umat[4];
    const float* bvec[4];
    wmat[0] = (const float*)d_in[2];  umat[0] = (const float*)d_in[3];  bvec[0] = (const float*)d_in[4];
    wmat[1] = (const float*)d_in[5];  umat[1] = (const float*)d_in[6];  bvec[1] = (const float*)d_in[7];
    wmat[2] = (const float*)d_in[8];  umat[2] = (const float*)d_in[9];  bvec[2] = (const float*)d_in[10];
    wmat[3] = (const float*)d_in[11]; umat[3] = (const float*)d_in[12]; bvec[3] = (const float*)d_in[13];
    const float* wo = (const float*)d_in[14];
    const float* bo = (const float*)d_in[15];

    __nv_bfloat16* px = 0;
    __nv_bfloat16* psb = 0;
    __nv_bfloat16* pub = 0;
    __nv_bfloat16* pwb = 0;
    __nv_bfloat16* pw1 = 0;
    __nv_bfloat16* pemb = 0;
    int* pflg = 0;
    cudaGetSymbolAddress((void**)&px,   g_x);
    cudaGetSymbolAddress((void**)&psb,  g_sb);
    cudaGetSymbolAddress((void**)&pub,  g_Ub);
    cudaGetSymbolAddress((void**)&pwb,  g_Wb);
    cudaGetSymbolAddress((void**)&pw1,  g_W1b);
    cudaGetSymbolAddress((void**)&pemb, g_embb);
    cudaGetSymbolAddress((void**)&pflg, g_flags);

    cudaFuncSetAttribute(k_projx, cudaFuncAttributeMaxDynamicSharedMemorySize, SMEM_PROJ);
    cudaFuncSetAttribute(k_layer, cudaFuncAttributeMaxDynamicSharedMemorySize, SMEM_LAYER);

    // 0: fused weight conversion (U1..4, W2..4)
    SrcPtrs sp;
    sp.p[0] = umat[0]; sp.p[1] = umat[1]; sp.p[2] = umat[2]; sp.p[3] = umat[3];
    sp.p[4] = wmat[1]; sp.p[5] = wmat[2]; sp.p[6] = wmat[3];
    k_convertW<<<7 * 262144 / 256, 256>>>(sp, pub, pwb);
    // 1-2: padded conversions
    k_padW1<<<(KPADE * HU + 255) / 256, 256>>>(wmat[0], pw1);
    {
        long nemb = (long)VOCABN * KPADE;
        k_padEmb<<<(unsigned)((nemb + 255) / 256), 256>>>(emb, pemb);
    }
    // 3: flag reset (once; covers all 4 layers)
    k_reset<<<2, 256>>>(pflg);

    dim3 blk(256, 1, 1);
    dim3 gproj(8, 18, 1);      // 144 persistent blocks, single wave
    dim3 glayer(8, 16, 1);     // 128 persistent blocks

    const int nw = HU * HU;
    for (int l = 0; l < 4; l++) {
        if (l == 0) {
            k_projx<<<gproj, blk, SMEM_PROJ>>>(pemb, tokens, pw1, bvec[0], px, KPADE, 1);
        } else {
            k_projx<<<gproj, blk, SMEM_PROJ>>>(psb, (const int*)0,
                                               pwb + (size_t)(l - 1) * nw, bvec[l], px, HU, 0);
        }
        k_layer<<<glayer, blk, SMEM_LAYER>>>(pub + (size_t)l * nw, px, psb,
                                             pflg + l * 16 * 8);
    }

    k_head<<<BATCHN / 8, 256>>>(psb, wo, bo, (float*)d_out);
}